// round 7
// baseline (speedup 1.0000x reference)
#include <cuda_runtime.h>
#include <cuda_bf16.h>
#include <cstdint>

// ============================================================================
// Problem: content[64,256], motion[64,512,128] -> M=32768 tokens
//   L1: [M,384]x[384,256]+b1, leaky(0.2)
//   L2: [M,256]x[256,512]+b2, leaky(0.2)
//   L3: [M,512]x[512,1152]+b3 -> out fp32
// Strategy: bf16x3 emulated-fp32 GEMM on mma.sync.m16n8k16.
//   C = Ahi*Bhi + Ahi*Blo + Alo*Bhi (A2B2 dropped, ~4e-6 rel).
// R7: CTA tile 256x128 (512 thr, 16 warps) -> B traffic halved;
//     Blo fragments resident -> 12 LDSM per ks instead of 14.
// ============================================================================

__device__ __nv_bfloat16 g_a1hi[12582912];   // [32768,384]
__device__ __nv_bfloat16 g_a1lo[12582912];
__device__ __nv_bfloat16 g_h1hi[8388608];    // [32768,256]
__device__ __nv_bfloat16 g_h1lo[8388608];
__device__ __nv_bfloat16 g_h2hi[16777216];   // [32768,512]
__device__ __nv_bfloat16 g_h2lo[16777216];
__device__ __nv_bfloat16 g_w1hi[98304],  g_w1lo[98304];    // [256,384]  (N,K)
__device__ __nv_bfloat16 g_w2hi[131072], g_w2lo[131072];   // [512,256]
__device__ __nv_bfloat16 g_w3hi[589824], g_w3lo[589824];   // [1152,512]

// ---- helpers ----
__device__ __forceinline__ uint32_t smem_u32(const void* p) {
    uint32_t a;
    asm("{ .reg .u64 t; cvta.to.shared.u64 t, %1; cvt.u32.u64 %0, t; }"
        : "=r"(a) : "l"(p));
    return a;
}
__device__ __forceinline__ void cp16(uint32_t dst, const void* src) {
    asm volatile("cp.async.cg.shared.global [%0], [%1], 16;"
                 :: "r"(dst), "l"(src) : "memory");
}
#define CP_COMMIT() asm volatile("cp.async.commit_group;" ::: "memory")
#define CP_WAIT(n)  asm volatile("cp.async.wait_group %0;" :: "n"(n) : "memory")

__device__ __forceinline__ void ldsm4(uint32_t* r, uint32_t addr) {
    asm volatile("ldmatrix.sync.aligned.m8n8.x4.shared.b16 {%0,%1,%2,%3}, [%4];"
                 : "=r"(r[0]), "=r"(r[1]), "=r"(r[2]), "=r"(r[3]) : "r"(addr));
}
__device__ __forceinline__ void hmma(float* c, const uint32_t* a, const uint32_t* b) {
    asm volatile(
        "mma.sync.aligned.m16n8k16.row.col.f32.bf16.bf16.f32 "
        "{%0,%1,%2,%3}, {%4,%5,%6,%7}, {%8,%9}, {%0,%1,%2,%3};"
        : "+f"(c[0]), "+f"(c[1]), "+f"(c[2]), "+f"(c[3])
        : "r"(a[0]), "r"(a[1]), "r"(a[2]), "r"(a[3]), "r"(b[0]), "r"(b[1]));
}

// ============================================================================
// prep kernels: fp32 -> bf16 hi/lo split
// ============================================================================
__global__ void prep_a(const float* __restrict__ content,
                       const float* __restrict__ motion,
                       __nv_bfloat16* __restrict__ hi,
                       __nv_bfloat16* __restrict__ lo)
{
    int idx = blockIdx.x * 256 + threadIdx.x;
    if (idx >= 32768 * 384) return;
    int m = idx / 384, k = idx - m * 384;
    float v = (k < 256) ? content[(m >> 9) * 256 + k]
                        : motion[(size_t)m * 128 + (k - 256)];
    __nv_bfloat16 h = __float2bfloat16(v);
    hi[idx] = h;
    lo[idx] = __float2bfloat16(v - __bfloat162float(h));
}

__global__ void prep_w(const float* __restrict__ W,
                       __nv_bfloat16* __restrict__ hi,
                       __nv_bfloat16* __restrict__ lo, int N, int K)
{
    int idx = blockIdx.x * 256 + threadIdx.x;
    if (idx >= N * K) return;
    int n = idx / K, k = idx - n * K;
    float v = W[(size_t)k * N + n];
    __nv_bfloat16 h = __float2bfloat16(v);
    hi[idx] = h;
    lo[idx] = __float2bfloat16(v - __bfloat162float(h));
}

// ============================================================================
// bf16x3 GEMM. CTA tile 256x128, BK=32. Each K-chunk stages 4 tiles
// {Ahi(256rows), Alo(256rows), Bhi(128rows), Blo(128rows)}.
// 16 warps: grid 4(M)x4(N), warp tile 64x32. ldmatrix.x4 fragments,
// a[4][4] + b[4][2] + bl[4][2] resident (12 LDSM / ks-step).
// Rows padded to 40 bf16 (80B). 2-stage pipeline, one __syncthreads/chunk.
// ============================================================================
#define PADK 40
#define A_TILE_B (256 * PADK * 2)    // 20480 B
#define B_TILE_B (128 * PADK * 2)    // 10240 B
#define STG_B    (2 * A_TILE_B + 2 * B_TILE_B)   // 61440 B per stage

template<int K, int NTOT, bool LEAKY, bool WRITE_F32>
__global__ __launch_bounds__(512, 1)
void gemm_hmma(const __nv_bfloat16* __restrict__ Ahi,
               const __nv_bfloat16* __restrict__ Alo,
               const __nv_bfloat16* __restrict__ Bhi,
               const __nv_bfloat16* __restrict__ Blo,
               const float* __restrict__ bias,
               float* __restrict__ Cout,
               __nv_bfloat16* __restrict__ NxtHi,
               __nv_bfloat16* __restrict__ NxtLo)
{
    constexpr int KC = K / 32;

    extern __shared__ __nv_bfloat16 smem[];
    const uint32_t smem_base = smem_u32(smem);

    const int tid  = threadIdx.x;
    const int lane = tid & 31;
    const int wid  = tid >> 5;
    const int g    = lane >> 2;
    const int t2   = (lane & 3) * 2;
    const int wm   = (wid >> 2) * 64;   // 0,64,128,192
    const int wn   = (wid & 3) * 32;    // 0,32,64,96

    const int rowBlock = blockIdx.y * 256;
    const int colBlock = blockIdx.x * 128;

    float acc[4][4][4];
    #pragma unroll
    for (int i = 0; i < 4; i++)
        #pragma unroll
        for (int j = 0; j < 4; j++)
            #pragma unroll
            for (int r = 0; r < 4; r++) acc[i][j][r] = 0.0f;

    // ldmatrix per-thread addressing (verified R4-R6)
    const int aRowT = ((lane >> 3) & 1) * 8 + (lane & 7);
    const int aColT = (lane >> 4) * 8;
    const int bRowT = ((lane >> 4) & 1) * 8 + (lane & 7);
    const int bColT = ((lane >> 3) & 1) * 8;

    // loader: A 2048 cp + B 1024 cp per chunk; 512 threads -> 6 cp each
    const int ldRow = tid >> 2;   // 0..127
    const int ldCh  = tid & 3;    // 0..3
    auto issue_chunk = [&](int c) {
        const int k0 = c * 32;
        const uint32_t sb = smem_base + (uint32_t)(c & 1) * STG_B;
        const uint32_t sAhi = sb;
        const uint32_t sAlo = sb + A_TILE_B;
        const uint32_t sBhi = sb + 2 * A_TILE_B;
        const uint32_t sBlo = sBhi + B_TILE_B;
        #pragma unroll
        for (int i = 0; i < 2; ++i) {
            const int r = ldRow + i * 128;
            const uint32_t off = (uint32_t)(r * PADK + ldCh * 8) * 2;
            const size_t ga = (size_t)(rowBlock + r) * K + k0 + ldCh * 8;
            cp16(sAhi + off, Ahi + ga);
            cp16(sAlo + off, Alo + ga);
        }
        {
            const uint32_t off = (uint32_t)(ldRow * PADK + ldCh * 8) * 2;
            const size_t gb = (size_t)(colBlock + ldRow) * K + k0 + ldCh * 8;
            cp16(sBhi + off, Bhi + gb);
            cp16(sBlo + off, Blo + gb);
        }
        CP_COMMIT();
    };

    issue_chunk(0);

    for (int c = 0; c < KC; ++c) {
        CP_WAIT(0);
        __syncthreads();
        if (c + 1 < KC) issue_chunk(c + 1);

        const uint32_t sb   = smem_base + (uint32_t)(c & 1) * STG_B;
        const uint32_t sAhi = sb;
        const uint32_t sAlo = sb + A_TILE_B;
        const uint32_t sBhi = sb + 2 * A_TILE_B;
        const uint32_t sBlo = sBhi + B_TILE_B;

        #pragma unroll
        for (int ks = 0; ks < 2; ++ks) {
            const int kb = ks * 16;
            uint32_t a[4][4], b[4][2], bl[4][2];
            const uint32_t aOff =
                (uint32_t)((wm + aRowT) * PADK + kb + aColT) * 2;
            const uint32_t bOff0 =
                (uint32_t)((wn + bRowT) * PADK + kb + bColT) * 2;
            const uint32_t bOff1 =
                (uint32_t)((wn + 16 + bRowT) * PADK + kb + bColT) * 2;

            // fragment loads: Ahi, Bhi, Blo (12 LDSM total this ks incl. Alo)
            #pragma unroll
            for (int mt = 0; mt < 4; ++mt)
                ldsm4(a[mt], sAhi + aOff + (uint32_t)(mt * 16 * PADK) * 2);
            {
                uint32_t r4[4];
                ldsm4(r4, sBhi + bOff0);
                b[0][0] = r4[0]; b[0][1] = r4[1];
                b[1][0] = r4[2]; b[1][1] = r4[3];
                ldsm4(r4, sBhi + bOff1);
                b[2][0] = r4[0]; b[2][1] = r4[1];
                b[3][0] = r4[2]; b[3][1] = r4[3];
                ldsm4(r4, sBlo + bOff0);
                bl[0][0] = r4[0]; bl[0][1] = r4[1];
                bl[1][0] = r4[2]; bl[1][1] = r4[3];
                ldsm4(r4, sBlo + bOff1);
                bl[2][0] = r4[0]; bl[2][1] = r4[1];
                bl[3][0] = r4[2]; bl[3][1] = r4[3];
            }
            // pass hh: Ahi*Bhi
            #pragma unroll
            for (int mt = 0; mt < 4; ++mt)
                #pragma unroll
                for (int nt = 0; nt < 4; ++nt)
                    hmma(acc[mt][nt], a[mt], b[nt]);
            // pass hl: Ahi*Blo
            #pragma unroll
            for (int mt = 0; mt < 4; ++mt)
                #pragma unroll
                for (int nt = 0; nt < 4; ++nt)
                    hmma(acc[mt][nt], a[mt], bl[nt]);
            // pass lh: Alo*Bhi
            #pragma unroll
            for (int mt = 0; mt < 4; ++mt)
                ldsm4(a[mt], sAlo + aOff + (uint32_t)(mt * 16 * PADK) * 2);
            #pragma unroll
            for (int mt = 0; mt < 4; ++mt)
                #pragma unroll
                for (int nt = 0; nt < 4; ++nt)
                    hmma(acc[mt][nt], a[mt], b[nt]);
        }
    }

    __syncthreads();

    // ---- epilogue: bias (+leaky) -> fp32 out, or bf16 hi/lo for next layer ----
    #pragma unroll
    for (int mt = 0; mt < 4; ++mt) {
        #pragma unroll
        for (int half = 0; half < 2; ++half) {
            const int grow = rowBlock + wm + mt * 16 + g + half * 8;
            #pragma unroll
            for (int nt = 0; nt < 4; ++nt) {
                const int gcol = colBlock + wn + nt * 8 + t2;
                float v0 = acc[mt][nt][half * 2 + 0] + bias[gcol];
                float v1 = acc[mt][nt][half * 2 + 1] + bias[gcol + 1];
                if (LEAKY) {
                    v0 = v0 >= 0.f ? v0 : 0.2f * v0;
                    v1 = v1 >= 0.f ? v1 : 0.2f * v1;
                }
                const size_t base = (size_t)grow * NTOT + gcol;
                if (WRITE_F32) {
                    float2 o; o.x = v0; o.y = v1;
                    *reinterpret_cast<float2*>(&Cout[base]) = o;
                } else {
                    __nv_bfloat16 h0 = __float2bfloat16(v0);
                    __nv_bfloat16 h1 = __float2bfloat16(v1);
                    __nv_bfloat16 l0 = __float2bfloat16(v0 - __bfloat162float(h0));
                    __nv_bfloat16 l1 = __float2bfloat16(v1 - __bfloat162float(h1));
                    *reinterpret_cast<__nv_bfloat162*>(&NxtHi[base]) =
                        __halves2bfloat162(h0, h1);
                    *reinterpret_cast<__nv_bfloat162*>(&NxtLo[base]) =
                        __halves2bfloat162(l0, l1);
                }
            }
        }
    }
}

// ============================================================================
// launcher
// ============================================================================
extern "C" void kernel_launch(void* const* d_in, const int* in_sizes, int n_in,
                              void* d_out, int out_size)
{
    (void)in_sizes; (void)n_in; (void)out_size;
    const float* content = (const float*)d_in[0];
    const float* motion  = (const float*)d_in[1];
    const float* W1 = (const float*)d_in[2];
    const float* b1 = (const float*)d_in[3];
    const float* W2 = (const float*)d_in[4];
    const float* b2 = (const float*)d_in[5];
    const float* W3 = (const float*)d_in[6];
    const float* b3 = (const float*)d_in[7];
    float* out = (float*)d_out;

    __nv_bfloat16 *a1hi, *a1lo, *h1hi, *h1lo, *h2hi, *h2lo;
    __nv_bfloat16 *w1hi, *w1lo, *w2hi, *w2lo, *w3hi, *w3lo;
    cudaGetSymbolAddress((void**)&a1hi, g_a1hi);
    cudaGetSymbolAddress((void**)&a1lo, g_a1lo);
    cudaGetSymbolAddress((void**)&h1hi, g_h1hi);
    cudaGetSymbolAddress((void**)&h1lo, g_h1lo);
    cudaGetSymbolAddress((void**)&h2hi, g_h2hi);
    cudaGetSymbolAddress((void**)&h2lo, g_h2lo);
    cudaGetSymbolAddress((void**)&w1hi, g_w1hi);
    cudaGetSymbolAddress((void**)&w1lo, g_w1lo);
    cudaGetSymbolAddress((void**)&w2hi, g_w2hi);
    cudaGetSymbolAddress((void**)&w2lo, g_w2lo);
    cudaGetSymbolAddress((void**)&w3hi, g_w3hi);
    cudaGetSymbolAddress((void**)&w3lo, g_w3lo);

    const int SMEM = 2 * STG_B;  // 122880 B
    cudaFuncSetAttribute((const void*)gemm_hmma<384, 256, true, false>,
                         cudaFuncAttributeMaxDynamicSharedMemorySize, SMEM);
    cudaFuncSetAttribute((const void*)gemm_hmma<256, 512, true, false>,
                         cudaFuncAttributeMaxDynamicSharedMemorySize, SMEM);
    cudaFuncSetAttribute((const void*)gemm_hmma<512, 1152, false, true>,
                         cudaFuncAttributeMaxDynamicSharedMemorySize, SMEM);

    // ---- prep: split inputs/weights into bf16 hi/lo ----
    prep_a<<<(32768 * 384 + 255) / 256, 256>>>(content, motion, a1hi, a1lo);
    prep_w<<<(256 * 384 + 255) / 256, 256>>>(W1, w1hi, w1lo, 256, 384);
    prep_w<<<(512 * 256 + 255) / 256, 256>>>(W2, w2hi, w2lo, 512, 256);
    prep_w<<<(1152 * 512 + 255) / 256, 256>>>(W3, w3hi, w3lo, 1152, 512);

    // ---- GEMM chain (M-blocks of 256) ----
    gemm_hmma<384, 256, true, false><<<dim3(2, 128), 512, SMEM>>>(
        a1hi, a1lo, w1hi, w1lo, b1, nullptr, h1hi, h1lo);
    gemm_hmma<256, 512, true, false><<<dim3(4, 128), 512, SMEM>>>(
        h1hi, h1lo, w2hi, w2lo, b2, nullptr, h2hi, h2lo);
    gemm_hmma<512, 1152, false, true><<<dim3(9, 128), 512, SMEM>>>(
        h2hi, h2lo, w3hi, w3lo, b3, out, nullptr, nullptr);
}